// round 11
// baseline (speedup 1.0000x reference)
#include <cuda_runtime.h>

#define KK     3
#define CIN    16
#define COUT   16
#define HH     64
#define WW     64
#define BB     4

#define TILE_H 4          // output rows per block
#define BX     64
#define BY     2          // 128 threads; each thread: 2 rows, 2 scalar channels
#define PX     2
#define FG     2          // output channels per block
#define CQ     4          // input channels per block (CIN split in 4)

#define SX_ROWS (TILE_H + 2)                 // 6
#define NOUT    (BB * COUT * HH * WW)        // 1,048,576

__device__ __forceinline__ float frcp(float x) {
    float r; asm("rcp.approx.ftz.f32 %0, %1;" : "=f"(r) : "f"(x)); return r;
}
__device__ __forceinline__ void redg_add(float* p, float v) {
    asm volatile("red.global.add.f32 [%0], %1;" :: "l"(p), "f"(v) : "memory");
}

// ---- zero the output buffer (poisoned by harness) ----
__global__ __launch_bounds__(128)
void zero_kernel(float* __restrict__ out) {
    const int i = blockIdx.x * 128 + threadIdx.x;       // float4 index
    reinterpret_cast<float4*>(out)[i] = make_float4(0.f, 0.f, 0.f, 0.f);
}

// Static SMEM (~9.2 KB):
//  sC: scalar coefficients for this block's 2 channels x 4 input channels:
//      per (c,p): 20 floats = [ch0: a0..a5,b1..b4][ch1: a0..a5,b1..b4]
//      -> 4*9*20 = 720 floats = 2880 B, read as 5 warp-uniform float4 per (c,p)
//  sX: 4 input-channel tiles, 6 rows x 66 cols = 6336 B
__global__ __launch_bounds__(BX * BY)
void kaconv_kernel(const float* __restrict__ x,
                   const float* __restrict__ A,
                   const float* __restrict__ Bc,
                   float* __restrict__ out) {
    __shared__ __align__(16) float sC[CQ * 9 * 20];   // 2880 B
    __shared__ float               sX[CQ * SX_ROWS * 66];

    const int tx  = threadIdx.x;
    const int ty  = threadIdx.y;
    const int tid = ty * BX + tx;
    const int h0  = blockIdx.x * TILE_H;
    const int b   = blockIdx.y;
    const int f0  = (blockIdx.z >> 2) * FG;
    const int cq  = blockIdx.z & 3;            // which c-quarter
    const int c0  = cq * CQ;

    // ---- stage scalar coefficients for channels c0..c0+3 ----
    for (int i = tid; i < CQ * 9 * 20; i += BX * BY) {
        int ii = i;
        const int k  = ii % 20; ii /= 20;
        const int p  = ii % 9;
        const int c  = c0 + ii / 9;
        const int f  = f0 + (k >= 10);
        const int kk = k % 10;
        float v;
        if (kk < 6) v = A [((f * CIN + c) * 9 + p) * 6 + kk];
        else        v = Bc[((f * CIN + c) * 9 + p) * 4 + (kk - 6)];
        sC[i] = v;
    }

    // ---- stage 4 input-channel tiles with zero-padded halo ----
    for (int i = tid; i < CQ * SX_ROWS * 66; i += BX * BY) {
        const int col = i % 66;
        const int r   = (i / 66) % SX_ROWS;
        const int cl  = i / (66 * SX_ROWS);
        const int gh  = h0 + r - 1;
        const int gw  = col - 1;
        float v = 0.0f;
        if (gh >= 0 && gh < HH && gw >= 0 && gw < WW)
            v = x[((b * CIN + c0 + cl) * HH + gh) * WW + gw];
        sX[(cl * SX_ROWS + r) * 66 + col] = v;
    }
    __syncthreads();

    const float4* sC4 = reinterpret_cast<const float4*>(sC);

    float acc00 = 0.f, acc01 = 0.f;   // pixel 0: ch0, ch1
    float acc10 = 0.f, acc11 = 0.f;   // pixel 1: ch0, ch1

    #pragma unroll 1
    for (int c = 0; c < CQ; c++) {
        // 4 rows x 3 cols register window covers both pixels' 3x3 windows
        float xr[PX + 2][3];
        #pragma unroll
        for (int r = 0; r < PX + 2; r++)
            #pragma unroll
            for (int j = 0; j < 3; j++)
                xr[r][j] = sX[(c * SX_ROWS + PX * ty + r) * 66 + (tx + j)];

        const float4* pc = sC4 + c * 45;   // 5 float4 per (c,p)
        #pragma unroll
        for (int p = 0; p < 9; p++) {
            const int di = p / 3, dj = p % 3;
            // warp-uniform broadcast loads
            const float4 q0 = pc[p * 5 + 0];  // ch0: a0 a1 a2 a3
            const float4 q1 = pc[p * 5 + 1];  // ch0: a4 a5 b1 b2
            const float4 q2 = pc[p * 5 + 2];  // ch0: b3 b4 | ch1: a0 a1
            const float4 q3 = pc[p * 5 + 3];  // ch1: a2 a3 a4 a5
            const float4 q4 = pc[p * 5 + 4];  // ch1: b1 b2 b3 b4

            #pragma unroll
            for (int py = 0; py < PX; py++) {
                const float xv = xr[py + di][dj];

                // ---- channel 0 ----
                float P = fmaf(q1.y, xv, q1.x);      // a5 x + a4
                P = fmaf(P, xv, q0.w);
                P = fmaf(P, xv, q0.z);
                P = fmaf(P, xv, q0.y);
                P = fmaf(P, xv, q0.x);
                float S = fmaf(q2.y, xv, q2.x);      // b4 x + b3
                S = fmaf(S, xv, q1.w);
                S = fmaf(S, xv, q1.z);
                S = S * xv;
                const float r0 = frcp(1.0f + fabsf(S));

                // ---- channel 1 ----
                float P1 = fmaf(q3.w, xv, q3.z);     // a5 x + a4
                P1 = fmaf(P1, xv, q3.y);
                P1 = fmaf(P1, xv, q3.x);
                P1 = fmaf(P1, xv, q2.w);
                P1 = fmaf(P1, xv, q2.z);
                float S1 = fmaf(q4.w, xv, q4.z);     // b4 x + b3
                S1 = fmaf(S1, xv, q4.y);
                S1 = fmaf(S1, xv, q4.x);
                S1 = S1 * xv;
                const float r1 = frcp(1.0f + fabsf(S1));

                if (py == 0) { acc00 = fmaf(P, r0, acc00); acc01 = fmaf(P1, r1, acc01); }
                else         { acc10 = fmaf(P, r0, acc10); acc11 = fmaf(P1, r1, acc11); }
            }
        }
    }

    // ---- accumulate into out via fire-and-forget global reductions ----
    // out starts at 0; four contributions per element (one per c-quarter).
    const int hA = h0 + PX * ty;
    const int w  = tx;
    float* op = out + ((b * COUT + f0) * HH + hA) * WW + w;
    redg_add(op,                  acc00);
    redg_add(op + WW,             acc10);
    redg_add(op + HH * WW,        acc01);
    redg_add(op + HH * WW + WW,   acc11);
}

extern "C" void kernel_launch(void* const* d_in, const int* in_sizes, int n_in,
                              void* d_out, int out_size) {
    const float* x  = (const float*)d_in[0];
    const float* A  = (const float*)d_in[1];
    const float* Bc = (const float*)d_in[2];
    float* out = (float*)d_out;

    zero_kernel<<<(NOUT / 4) / 128, 128>>>(out);    // 2048 blocks, 4 MB zeros

    dim3 grid(HH / TILE_H, BB, (COUT / FG) * (CIN / CQ));  // (16,4,32) = 2048 blocks
    dim3 block(BX, BY, 1);                                  // 128 threads
    kaconv_kernel<<<grid, block>>>(x, A, Bc, out);
}

// round 12
// speedup vs baseline: 1.1394x; 1.1394x over previous
#include <cuda_runtime.h>

#define KK     3
#define CIN    16
#define COUT   16
#define HH     64
#define WW     64
#define BB     4

#define TILE_H 4          // output rows per block
#define BX     64
#define BY     2          // 128 threads; each thread: 2 rows, 1 packed f-pair
#define PX     2
#define FG     2          // output channels per block
#define CQ     4          // input channels per block (CIN split in 4)

#define SX_ROWS (TILE_H + 2)                 // 6
#define NOUT    (BB * COUT * HH * WW)        // 1,048,576

typedef unsigned long long ull;

// ---------------- Blackwell packed f32x2 helpers ----------------
__device__ __forceinline__ ull pk2s(float v) {            // (v, v)
    ull r; asm("mov.b64 %0, {%1, %1};" : "=l"(r) : "f"(v)); return r;
}
__device__ __forceinline__ void upk2(ull v, float& lo, float& hi) {
    asm("mov.b64 {%0, %1}, %2;" : "=f"(lo), "=f"(hi) : "l"(v));
}
__device__ __forceinline__ ull pk2(float lo, float hi) {
    ull r; asm("mov.b64 %0, {%1, %2};" : "=l"(r) : "f"(lo), "f"(hi)); return r;
}
__device__ __forceinline__ ull ffma2(ull a, ull b, ull c) {
    ull d; asm("fma.rn.f32x2 %0, %1, %2, %3;" : "=l"(d) : "l"(a), "l"(b), "l"(c)); return d;
}
__device__ __forceinline__ ull fmul2(ull a, ull b) {
    ull d; asm("mul.rn.f32x2 %0, %1, %2;" : "=l"(d) : "l"(a), "l"(b)); return d;
}
__device__ __forceinline__ float frcp(float x) {
    float r; asm("rcp.approx.ftz.f32 %0, %1;" : "=f"(r) : "f"(x)); return r;
}
__device__ __forceinline__ void redg_add(float* p, float v) {
    asm volatile("red.global.add.f32 [%0], %1;" :: "l"(p), "f"(v) : "memory");
}

// ---- zero the output buffer (poisoned by harness) ----
__global__ __launch_bounds__(128)
void zero_kernel(float* __restrict__ out) {
    const int i = blockIdx.x * 128 + threadIdx.x;       // float4 index
    reinterpret_cast<float4*>(out)[i] = make_float4(0.f, 0.f, 0.f, 0.f);
}

// Static SMEM (~9.1 KB):
//  sC: packed coefficients, this block's f-pair x its 4 input channels:
//      per (c,p): 10 float2 (6 A-pairs, 4 B-pairs) -> 360 float2 = 2880 B
//  sX: 4 input-channel tiles, 6 rows x 66 cols = 6336 B
__global__ __launch_bounds__(BX * BY, 8)    // cap 64 regs, >=8 blocks/SM
void kaconv_kernel(const float* __restrict__ x,
                   const float* __restrict__ A,
                   const float* __restrict__ Bc,
                   float* __restrict__ out) {
    __shared__ __align__(16) ull  sC[CQ * 9 * 10];   // 360 slots = 2880 B
    __shared__ float              sX[CQ * SX_ROWS * 66];

    const int tx  = threadIdx.x;
    const int ty  = threadIdx.y;
    const int tid = ty * BX + tx;
    const int h0  = blockIdx.x * TILE_H;
    const int b   = blockIdx.y;
    const int f0  = (blockIdx.z >> 2) * FG;
    const int cq  = blockIdx.z & 3;            // which c-quarter
    const int c0  = cq * CQ;

    // ---- stage packed coefficients for channels c0..c0+3 ----
    float2* sCf = reinterpret_cast<float2*>(sC);
    for (int i = tid; i < CQ * 9 * 10; i += BX * BY) {
        int ii = i;
        const int k = ii % 10; ii /= 10;
        const int p = ii % 9;
        const int c = c0 + ii / 9;
        float lo, hi;
        if (k < 6) {
            lo = A[(( f0      * CIN + c) * 9 + p) * 6 + k];
            hi = A[(((f0 + 1) * CIN + c) * 9 + p) * 6 + k];
        } else {
            const int j = k - 6;
            lo = Bc[(( f0      * CIN + c) * 9 + p) * 4 + j];
            hi = Bc[(((f0 + 1) * CIN + c) * 9 + p) * 4 + j];
        }
        sCf[i] = make_float2(lo, hi);
    }

    // ---- stage 4 input-channel tiles with zero-padded halo ----
    for (int i = tid; i < CQ * SX_ROWS * 66; i += BX * BY) {
        const int col = i % 66;
        const int r   = (i / 66) % SX_ROWS;
        const int cl  = i / (66 * SX_ROWS);
        const int gh  = h0 + r - 1;
        const int gw  = col - 1;
        float v = 0.0f;
        if (gh >= 0 && gh < HH && gw >= 0 && gw < WW)
            v = x[((b * CIN + c0 + cl) * HH + gh) * WW + gw];
        sX[(cl * SX_ROWS + r) * 66 + col] = v;
    }
    __syncthreads();

    const ulonglong2* sC2 = reinterpret_cast<const ulonglong2*>(sC);
    // per-thread bases: all subsequent LDS become base + immediate offsets
    const float* xbase = sX + PX * ty * 66 + tx;

    ull acc0 = 0ull, acc1 = 0ull;

    #pragma unroll            // FULL unroll: CQ=4 iterations, immediate LDS offsets
    for (int c = 0; c < CQ; c++) {
        // 4 rows x 3 cols register window covers both pixels' 3x3 windows
        float xr[PX + 2][3];
        #pragma unroll
        for (int r = 0; r < PX + 2; r++)
            #pragma unroll
            for (int j = 0; j < 3; j++)
                xr[r][j] = xbase[(c * SX_ROWS + r) * 66 + j];

        const ulonglong2* pc = sC2 + c * 45;   // 5 ulonglong2 per (c,p)
        #pragma unroll
        for (int p = 0; p < 9; p++) {
            const int di = p / 3, dj = p % 3;
            const ulonglong2 u0 = pc[p * 5 + 0];  // {A0, A1}
            const ulonglong2 u1 = pc[p * 5 + 1];  // {A2, A3}
            const ulonglong2 u2 = pc[p * 5 + 2];  // {A4, A5}
            const ulonglong2 u3 = pc[p * 5 + 3];  // {B1, B2}
            const ulonglong2 u4 = pc[p * 5 + 4];  // {B3, B4}

            #pragma unroll
            for (int py = 0; py < PX; py++) {
                const ull X = pk2s(xr[py + di][dj]);

                // P = a0 + ... + a5 x^5 (Horner, packed over f-pair)
                ull P = ffma2(u2.y, X, u2.x);
                P = ffma2(P, X, u1.y);
                P = ffma2(P, X, u1.x);
                P = ffma2(P, X, u0.y);
                P = ffma2(P, X, u0.x);

                // S = x*(b1 + x*(b2 + x*(b3 + x*b4)))
                ull T = ffma2(u4.y, X, u4.x);
                T = ffma2(T, X, u3.y);
                T = ffma2(T, X, u3.x);
                T = fmul2(T, X);

                // Q = 1 + |S| (abs free on FADD); R = 1/Q via MUFU
                float t0, t1; upk2(T, t0, t1);
                const ull R = pk2(frcp(1.0f + fabsf(t0)), frcp(1.0f + fabsf(t1)));

                if (py == 0) acc0 = ffma2(P, R, acc0);
                else         acc1 = ffma2(P, R, acc1);
            }
        }
    }

    // ---- accumulate into out via fire-and-forget global reductions ----
    // out starts at 0; four contributions per element (one per c-quarter).
    const int hA = h0 + PX * ty;
    const int w  = tx;
    float a0, a1, b0, b1;
    upk2(acc0, a0, a1);
    upk2(acc1, b0, b1);
    float* op = out + ((b * COUT + f0) * HH + hA) * WW + w;
    redg_add(op,                  a0);
    redg_add(op + WW,             b0);
    redg_add(op + HH * WW,        a1);
    redg_add(op + HH * WW + WW,   b1);
}

extern "C" void kernel_launch(void* const* d_in, const int* in_sizes, int n_in,
                              void* d_out, int out_size) {
    const float* x  = (const float*)d_in[0];
    const float* A  = (const float*)d_in[1];
    const float* Bc = (const float*)d_in[2];
    float* out = (float*)d_out;

    zero_kernel<<<(NOUT / 4) / 128, 128>>>(out);    // 2048 blocks, 4 MB zeros

    dim3 grid(HH / TILE_H, BB, (COUT / FG) * (CIN / CQ));  // (16,4,32) = 2048 blocks
    dim3 block(BX, BY, 1);                                  // 128 threads
    kaconv_kernel<<<grid, block>>>(x, A, Bc, out);
}

// round 13
// speedup vs baseline: 1.3082x; 1.1481x over previous
#include <cuda_runtime.h>

#define KK     3
#define CIN    16
#define COUT   16
#define HH     64
#define WW     64
#define BB     4

#define TILE_H 8          // output rows per block
#define BX     64
#define BY     2          // 128 threads; each thread: 4 rows, 1 packed f-pair
#define PX     4          // pixels (rows) per thread
#define FG     2          // output channels per block
#define CQ     4          // input channels per block (CIN split in 4)

#define SX_ROWS (TILE_H + 2)                 // 10
#define NOUT    (BB * COUT * HH * WW)        // 1,048,576

typedef unsigned long long ull;

// ---------------- Blackwell packed f32x2 helpers ----------------
__device__ __forceinline__ ull pk2s(float v) {            // (v, v)
    ull r; asm("mov.b64 %0, {%1, %1};" : "=l"(r) : "f"(v)); return r;
}
__device__ __forceinline__ void upk2(ull v, float& lo, float& hi) {
    asm("mov.b64 {%0, %1}, %2;" : "=f"(lo), "=f"(hi) : "l"(v));
}
__device__ __forceinline__ ull pk2(float lo, float hi) {
    ull r; asm("mov.b64 %0, {%1, %2};" : "=l"(r) : "f"(lo), "f"(hi)); return r;
}
__device__ __forceinline__ ull ffma2(ull a, ull b, ull c) {
    ull d; asm("fma.rn.f32x2 %0, %1, %2, %3;" : "=l"(d) : "l"(a), "l"(b), "l"(c)); return d;
}
__device__ __forceinline__ ull fmul2(ull a, ull b) {
    ull d; asm("mul.rn.f32x2 %0, %1, %2;" : "=l"(d) : "l"(a), "l"(b)); return d;
}
__device__ __forceinline__ float frcp(float x) {
    float r; asm("rcp.approx.ftz.f32 %0, %1;" : "=f"(r) : "f"(x)); return r;
}
__device__ __forceinline__ void redg_add(float* p, float v) {
    asm volatile("red.global.add.f32 [%0], %1;" :: "l"(p), "f"(v) : "memory");
}

// ---- zero the output buffer (poisoned by harness) ----
__global__ __launch_bounds__(128)
void zero_kernel(float* __restrict__ out) {
    const int i = blockIdx.x * 128 + threadIdx.x;       // float4 index
    reinterpret_cast<float4*>(out)[i] = make_float4(0.f, 0.f, 0.f, 0.f);
}

// Static SMEM (~13.1 KB):
//  sC: packed coefficients, this block's f-pair x its 4 input channels:
//      per (c,p): 10 float2 (6 A-pairs, 4 B-pairs) -> 360 float2 = 2880 B
//  sX: 4 input-channel tiles, 10 rows x 66 cols = 10560 B
__global__ __launch_bounds__(BX * BY, 7)    // 73-reg budget, 7 blocks/SM
void kaconv_kernel(const float* __restrict__ x,
                   const float* __restrict__ A,
                   const float* __restrict__ Bc,
                   float* __restrict__ out) {
    __shared__ __align__(16) ull  sC[CQ * 9 * 10];   // 360 slots = 2880 B
    __shared__ float              sX[CQ * SX_ROWS * 66];

    const int tx  = threadIdx.x;
    const int ty  = threadIdx.y;
    const int tid = ty * BX + tx;
    const int h0  = blockIdx.x * TILE_H;
    const int b   = blockIdx.y;
    const int f0  = (blockIdx.z >> 2) * FG;
    const int cq  = blockIdx.z & 3;            // which c-quarter
    const int c0  = cq * CQ;

    // ---- stage packed coefficients for channels c0..c0+3 ----
    float2* sCf = reinterpret_cast<float2*>(sC);
    for (int i = tid; i < CQ * 9 * 10; i += BX * BY) {
        int ii = i;
        const int k = ii % 10; ii /= 10;
        const int p = ii % 9;
        const int c = c0 + ii / 9;
        float lo, hi;
        if (k < 6) {
            lo = A[(( f0      * CIN + c) * 9 + p) * 6 + k];
            hi = A[(((f0 + 1) * CIN + c) * 9 + p) * 6 + k];
        } else {
            const int j = k - 6;
            lo = Bc[(( f0      * CIN + c) * 9 + p) * 4 + j];
            hi = Bc[(((f0 + 1) * CIN + c) * 9 + p) * 4 + j];
        }
        sCf[i] = make_float2(lo, hi);
    }

    // ---- stage 4 input-channel tiles with zero-padded halo ----
    for (int i = tid; i < CQ * SX_ROWS * 66; i += BX * BY) {
        const int col = i % 66;
        const int r   = (i / 66) % SX_ROWS;
        const int cl  = i / (66 * SX_ROWS);
        const int gh  = h0 + r - 1;
        const int gw  = col - 1;
        float v = 0.0f;
        if (gh >= 0 && gh < HH && gw >= 0 && gw < WW)
            v = x[((b * CIN + c0 + cl) * HH + gh) * WW + gw];
        sX[(cl * SX_ROWS + r) * 66 + col] = v;
    }
    __syncthreads();

    const ulonglong2* sC2 = reinterpret_cast<const ulonglong2*>(sC);
    const float* xbase = sX + PX * ty * 66 + tx;

    ull acc[PX];
    #pragma unroll
    for (int i = 0; i < PX; i++) acc[i] = 0ull;

    #pragma unroll 1          // keep regs low; unroll proven neutral (R12)
    for (int c = 0; c < CQ; c++) {
        // 6 rows x 3 cols register window covers all 4 pixels' 3x3 windows
        float xr[PX + 2][3];
        #pragma unroll
        for (int r = 0; r < PX + 2; r++)
            #pragma unroll
            for (int j = 0; j < 3; j++)
                xr[r][j] = xbase[(c * SX_ROWS + r) * 66 + j];

        const ulonglong2* pc = sC2 + c * 45;   // 5 ulonglong2 per (c,p)
        #pragma unroll
        for (int p = 0; p < 9; p++) {
            const int di = p / 3, dj = p % 3;
            const ulonglong2 u0 = pc[p * 5 + 0];  // {A0, A1}
            const ulonglong2 u1 = pc[p * 5 + 1];  // {A2, A3}
            const ulonglong2 u2 = pc[p * 5 + 2];  // {A4, A5}
            const ulonglong2 u3 = pc[p * 5 + 3];  // {B1, B2}
            const ulonglong2 u4 = pc[p * 5 + 4];  // {B3, B4}

            #pragma unroll
            for (int py = 0; py < PX; py++) {
                const ull X = pk2s(xr[py + di][dj]);

                // P = a0 + ... + a5 x^5 (Horner, packed over f-pair)
                ull P = ffma2(u2.y, X, u2.x);
                P = ffma2(P, X, u1.y);
                P = ffma2(P, X, u1.x);
                P = ffma2(P, X, u0.y);
                P = ffma2(P, X, u0.x);

                // S = x*(b1 + x*(b2 + x*(b3 + x*b4)))
                ull T = ffma2(u4.y, X, u4.x);
                T = ffma2(T, X, u3.y);
                T = ffma2(T, X, u3.x);
                T = fmul2(T, X);

                // Q = 1 + |S| (abs free on FADD); R = 1/Q via MUFU
                float t0, t1; upk2(T, t0, t1);
                const ull R = pk2(frcp(1.0f + fabsf(t0)), frcp(1.0f + fabsf(t1)));

                acc[py] = ffma2(P, R, acc[py]);
            }
        }
    }

    // ---- accumulate into out via fire-and-forget global reductions ----
    // out starts at 0; four contributions per element (one per c-quarter).
    const int hA = h0 + PX * ty;
    const int w  = tx;
    float* op = out + ((b * COUT + f0) * HH + hA) * WW + w;
    #pragma unroll
    for (int py = 0; py < PX; py++) {
        float lo, hi;
        upk2(acc[py], lo, hi);
        redg_add(op + py * WW,           lo);
        redg_add(op + HH * WW + py * WW, hi);
    }
}

extern "C" void kernel_launch(void* const* d_in, const int* in_sizes, int n_in,
                              void* d_out, int out_size) {
    const float* x  = (const float*)d_in[0];
    const float* A  = (const float*)d_in[1];
    const float* Bc = (const float*)d_in[2];
    float* out = (float*)d_out;

    zero_kernel<<<(NOUT / 4) / 128, 128>>>(out);    // 2048 blocks, 4 MB zeros

    dim3 grid(HH / TILE_H, BB, (COUT / FG) * (CIN / CQ));  // (8,4,32) = 1024 blocks
    dim3 block(BX, BY, 1);                                  // 128 threads
    kaconv_kernel<<<grid, block>>>(x, A, Bc, out);
}